// round 6
// baseline (speedup 1.0000x reference)
#include <cuda_runtime.h>
#include <math.h>
#include <stdint.h>

#define BSZ 512
#define DSZ 256
#define EPSF 1e-8f
#define MARGINF 0.3f
#define UWF 0.05f

// ---------------------------------------------------------------------------
// scratch (__device__ globals; no cudaMalloc allowed)
// ---------------------------------------------------------------------------
__device__ unsigned long long g_pos[BSZ * 16];   // per (anchor, j-tile) packed max
__device__ unsigned long long g_neg[BSZ * 16];   // per (anchor, j-tile) packed min
__device__ float g_bl[128], g_bv[128], g_bu[128];
__device__ unsigned int g_bar_ctr = 0;           // wraps via atomicInc(.,127)
__device__ unsigned int g_bar_rel = 0;           // parity flips once per launch
__device__ unsigned int g_ctr2 = 0;              // wraps via atomicInc(.,127)

// packed f32x2 FMA: d = a*b + d (lane-wise IEEE fma)
#define FMA2(d, a, b) \
    asm("fma.rn.f32x2 %0, %1, %2, %0;" : "+l"(d) : "l"(a), "l"(b))

__device__ __forceinline__ uint32_t smem_u32(const void* p) {
    uint32_t r;
    asm("{ .reg .u64 t; cvta.to.shared.u64 t, %1; cvt.u32.u64 %0, t; }"
        : "=r"(r) : "l"(p));
    return r;
}

// ---------------------------------------------------------------------------
// Fused kernel: distance tiles + mining, grid-wide barrier, distributed
// finalize, last-block scalar reduce. grid (16,8) = 128 blocks, 128 threads.
// ---------------------------------------------------------------------------
__global__ __launch_bounds__(128) void k_all(const float* __restrict__ E,
                                             const float* __restrict__ U,
                                             const int*   __restrict__ L,
                                             float* __restrict__ out) {
    __shared__ __align__(16) float As[32][68];   // [d_local][i_local] (64+pad)
    __shared__ __align__(16) float Bs[32][72];   // [d_local][2*j_local] DUPLICATED
    __shared__ float sni[64], snj[32];
    __shared__ int   sli[64], slj[32];
    __shared__ float s_al[4], s_av[4], s_au[4];
    __shared__ float s_fin[12];
    __shared__ int   s_flag;

    const int t = threadIdx.x;
    const int i0 = blockIdx.y * 64;
    const int j0 = blockIdx.x * 32;
    const int bid = blockIdx.y * 16 + blockIdx.x;   // 0..127
    const int tx = t & 7;         // j-quad
    const int ty = t >> 3;        // i-quad (0..15)
    const int lane = t & 31, w = t >> 5;
    const float4* E4 = (const float4*)E;
    const float4* U4 = (const float4*)U;

    // loader lanes
    const int ar = t >> 1, ah = t & 1;   // A: 64 rows x 2 threads, 4 f4 each
    const int br = t >> 2, bh = t & 3;   // B: 32 rows x 4 threads, 2 f4 each

    if (t < 64) sli[t] = L[i0 + t];
    if (t < 32) slj[t] = L[j0 + t];

    // 8 packed accumulators
    uint64_t accP[4] = {0, 0, 0, 0}, accQ[4] = {0, 0, 0, 0};
    float nA = 0.f, nB = 0.f;

    const uint32_t as_base = smem_u32(&As[0][4 * ty]);
    const uint32_t bs_base = smem_u32(&Bs[0][8 * tx]);

    float4 pa[4], pb[2];
#pragma unroll
    for (int k = 0; k < 4; k++) pa[k] = E4[(i0 + ar) * 64 + ah + 2 * k];
#pragma unroll
    for (int k = 0; k < 2; k++) pb[k] = E4[(j0 + br) * 64 + bh + 4 * k];

#pragma unroll 1
    for (int ch = 0; ch < 8; ch++) {
#pragma unroll
        for (int k = 0; k < 4; k++) {
            nA = fmaf(pa[k].x, pa[k].x, nA); nA = fmaf(pa[k].y, pa[k].y, nA);
            nA = fmaf(pa[k].z, pa[k].z, nA); nA = fmaf(pa[k].w, pa[k].w, nA);
        }
#pragma unroll
        for (int k = 0; k < 2; k++) {
            nB = fmaf(pb[k].x, pb[k].x, nB); nB = fmaf(pb[k].y, pb[k].y, nB);
            nB = fmaf(pb[k].z, pb[k].z, nB); nB = fmaf(pb[k].w, pb[k].w, nB);
        }

        // stage A (transposed)
#pragma unroll
        for (int k = 0; k < 4; k++) {
            int q = ah + 2 * k;
            As[q * 4 + 0][ar] = pa[k].x;
            As[q * 4 + 1][ar] = pa[k].y;
            As[q * 4 + 2][ar] = pa[k].z;
            As[q * 4 + 3][ar] = pa[k].w;
        }
        // stage B (transposed + duplicated: {v,v} pairs for direct b64 loads)
#pragma unroll
        for (int k = 0; k < 2; k++) {
            int q = bh + 4 * k;
            float2 v;
            v.x = v.y = pb[k].x; *(float2*)&Bs[q * 4 + 0][2 * br] = v;
            v.x = v.y = pb[k].y; *(float2*)&Bs[q * 4 + 1][2 * br] = v;
            v.x = v.y = pb[k].z; *(float2*)&Bs[q * 4 + 2][2 * br] = v;
            v.x = v.y = pb[k].w; *(float2*)&Bs[q * 4 + 3][2 * br] = v;
        }
        __syncthreads();

        if (ch < 7) {
#pragma unroll
            for (int k = 0; k < 4; k++)
                pa[k] = E4[(i0 + ar) * 64 + (ch + 1) * 8 + ah + 2 * k];
#pragma unroll
            for (int k = 0; k < 2; k++)
                pb[k] = E4[(j0 + br) * 64 + (ch + 1) * 8 + bh + 4 * k];
        }

#pragma unroll
        for (int d = 0; d < 32; d++) {
            uint64_t a01, a23, bb0, bb1, bb2, bb3;
            asm("ld.shared.v2.u64 {%0, %1}, [%2];"
                : "=l"(a01), "=l"(a23) : "r"(as_base + d * (68 * 4)));
            asm("ld.shared.v2.u64 {%0, %1}, [%2];"
                : "=l"(bb0), "=l"(bb1) : "r"(bs_base + d * (72 * 4)));
            asm("ld.shared.v2.u64 {%0, %1}, [%2];"
                : "=l"(bb2), "=l"(bb3) : "r"(bs_base + d * (72 * 4) + 16));
            FMA2(accP[0], a01, bb0);
            FMA2(accP[1], a01, bb1);
            FMA2(accP[2], a01, bb2);
            FMA2(accP[3], a01, bb3);
            FMA2(accQ[0], a23, bb0);
            FMA2(accQ[1], a23, bb1);
            FMA2(accQ[2], a23, bb2);
            FMA2(accQ[3], a23, bb3);
        }
        __syncthreads();
    }

    // publish row norms
    nA += __shfl_xor_sync(0xffffffffu, nA, 1);
    if (ah == 0) sni[ar] = nA;
    nB += __shfl_xor_sync(0xffffffffu, nB, 1);
    nB += __shfl_xor_sync(0xffffffffu, nB, 2);
    if (bh == 0) snj[br] = nB;
    __syncthreads();

    // unpack dots
    float dt[4][4];
#pragma unroll
    for (int c = 0; c < 4; c++) {
        uint32_t lo, hi;
        asm("mov.b64 {%0, %1}, %2;" : "=r"(lo), "=r"(hi) : "l"(accP[c]));
        dt[0][c] = __uint_as_float(lo); dt[1][c] = __uint_as_float(hi);
        asm("mov.b64 {%0, %1}, %2;" : "=r"(lo), "=r"(hi) : "l"(accQ[c]));
        dt[2][c] = __uint_as_float(lo); dt[3][c] = __uint_as_float(hi);
    }

    float njv[4]; int ljv[4];
#pragma unroll
    for (int c = 0; c < 4; c++) { njv[c] = snj[4 * tx + c]; ljv[c] = slj[4 * tx + c]; }

#pragma unroll
    for (int r = 0; r < 4; r++) {
        const int gi = i0 + 4 * ty + r;
        const int la = sli[4 * ty + r];
        const float nir = sni[4 * ty + r];

        unsigned long long bp = 0ull;   // pos: max dist, same label, j!=i; tie -> low j
        unsigned long long bn = ~0ull;  // neg: min dist, diff label; tie -> low j
#pragma unroll
        for (int c = 0; c < 4; c++) {
            const int jg = j0 + 4 * tx + c;
            float dist = sqrtf(fmaxf(nir + njv[c] - 2.f * dt[r][c], 0.f)) + EPSF;
            unsigned long long enc = ((unsigned long long)__float_as_uint(dist) << 32);
            if (ljv[c] == la && jg != gi) {
                unsigned long long cnd = enc | (0xFFFFFFFFu - (unsigned)jg);
                if (cnd > bp) bp = cnd;
            }
            if (ljv[c] != la) {
                unsigned long long cnd = enc | (unsigned)jg;
                if (cnd < bn) bn = cnd;
            }
        }
#pragma unroll
        for (int off = 4; off; off >>= 1) {
            unsigned long long o = __shfl_down_sync(0xffffffffu, bp, off, 8);
            if (o > bp) bp = o;
            o = __shfl_down_sync(0xffffffffu, bn, off, 8);
            if (o < bn) bn = o;
        }
        if (tx == 0) {
            g_pos[gi * 16 + blockIdx.x] = bp;
            g_neg[gi * 16 + blockIdx.x] = bn;
        }
    }

    // ===================== grid-wide barrier (parity release) ================
    __threadfence();
    __syncthreads();
    if (t == 0) {
        unsigned ph = *(volatile unsigned*)&g_bar_rel;  // read parity BEFORE arriving
        unsigned r = atomicInc(&g_bar_ctr, 127);
        if (r == 127) {
            __threadfence();
            *(volatile unsigned*)&g_bar_rel = ph ^ 1u;  // release
        } else {
            while (*(volatile unsigned*)&g_bar_rel == ph) __nanosleep(64);
        }
    }
    __syncthreads();
    __threadfence();

    // ===================== distributed finalize: 4 anchors/block =============
    // warp w -> anchor ia; lanes 0-15 = pos side, 16-31 = neg side.
    {
        const int ia = bid * 4 + w;
        const int side = lane >> 4;
        const int l16 = lane & 15;

        unsigned long long p =
            side ? *(volatile unsigned long long*)&g_neg[ia * 16 + l16]
                 : *(volatile unsigned long long*)&g_pos[ia * 16 + l16];
#pragma unroll
        for (int off = 8; off; off >>= 1) {
            unsigned long long o = __shfl_xor_sync(0xffffffffu, p, off, 16);
            if (side ? (o < p) : (o > p)) p = o;
        }
        unsigned long long ppos = __shfl_sync(0xffffffffu, p, 0);
        unsigned long long pneg = __shfl_sync(0xffffffffu, p, 16);
        const bool valid = (ppos != 0ull) && (pneg != ~0ull);
        const float dp = __uint_as_float((uint32_t)(ppos >> 32));
        const float dn = __uint_as_float((uint32_t)(pneg >> 32));
        const int jp = (ppos != 0ull) ? (int)(0xFFFFFFFFu - (uint32_t)ppos) : 0;
        const int jn = (pneg != ~0ull) ? (int)(uint32_t)pneg : 0;
        const int jx = side ? jn : jp;

        // W = sum_d u_ia^2 (e_ia - e_jx)^2 ; half 0 also sums clipped u.
        float W = 0.f, us = 0.f;
#pragma unroll
        for (int k = 0; k < 4; k++) {
            int q = l16 + 16 * k;
            float4 ui = U4[ia * 64 + q];
            float4 ei = E4[ia * 64 + q];
            float4 ej = E4[jx * 64 + q];
            ui.x = fminf(fmaxf(ui.x, 1e-6f), 1.f);
            ui.y = fminf(fmaxf(ui.y, 1e-6f), 1.f);
            ui.z = fminf(fmaxf(ui.z, 1e-6f), 1.f);
            ui.w = fminf(fmaxf(ui.w, 1e-6f), 1.f);
            float df;
            df = ei.x - ej.x; W = fmaf(ui.x * ui.x, df * df, W);
            df = ei.y - ej.y; W = fmaf(ui.y * ui.y, df * df, W);
            df = ei.z - ej.z; W = fmaf(ui.z * ui.z, df * df, W);
            df = ei.w - ej.w; W = fmaf(ui.w * ui.w, df * df, W);
            if (side == 0) us += ((ui.x + ui.y) + (ui.z + ui.w));
        }
#pragma unroll
        for (int off = 8; off; off >>= 1) {
            W  += __shfl_xor_sync(0xffffffffu, W, off, 16);
            us += __shfl_xor_sync(0xffffffffu, us, off, 16);
        }
        float Wn = __shfl_sync(0xffffffffu, W, 16);
        if (lane == 0) {
            float wp = W, wn = Wn;
            float up2 = wp / (dp * dp) + EPSF;
            float un2 = wn / (dn * dn) + EPSF;
            float sig = sqrtf(up2 + un2 + EPSF);
            float me = MARGINF + UWF * sig;
            float z = (dp - dn + me) / sig;
            float sp = fmaxf(z, 0.f) + log1pf(expf(-fabsf(z)));
            s_al[w] = valid ? sig * sp : 0.f;
            s_av[w] = valid ? 1.f : 0.f;
            s_au[w] = us;
        }
    }
    __syncthreads();

    if (t == 0) {
        g_bl[bid] = (s_al[0] + s_al[1]) + (s_al[2] + s_al[3]);
        g_bv[bid] = (s_av[0] + s_av[1]) + (s_av[2] + s_av[3]);
        g_bu[bid] = (s_au[0] + s_au[1]) + (s_au[2] + s_au[3]);
        __threadfence();
        s_flag = (atomicInc(&g_ctr2, 127) == 127) ? 1 : 0;
    }
    __syncthreads();
    if (!s_flag) return;
    __threadfence();

    // ===================== final scalar (globally last block) ================
    {
        float l = *(volatile float*)&g_bl[t];
        float v = *(volatile float*)&g_bv[t];
        float u = *(volatile float*)&g_bu[t];
#pragma unroll
        for (int off = 16; off; off >>= 1) {
            l += __shfl_down_sync(0xffffffffu, l, off);
            v += __shfl_down_sync(0xffffffffu, v, off);
            u += __shfl_down_sync(0xffffffffu, u, off);
        }
        if (lane == 0) {
            s_fin[w] = l; s_fin[4 + w] = v; s_fin[8 + w] = u;
        }
        __syncthreads();
        if (t == 0) {
            float L = (s_fin[0] + s_fin[1]) + (s_fin[2] + s_fin[3]);
            float V = (s_fin[4] + s_fin[5]) + (s_fin[6] + s_fin[7]);
            float Uu = (s_fin[8] + s_fin[9]) + (s_fin[10] + s_fin[11]);
            float total = L / fmaxf(V, 1.0f) + UWF * (Uu / (float)(BSZ * DSZ));
            if (isnan(total) || isinf(total)) total = 0.f;
            out[0] = total;
        }
    }
}

// ---------------------------------------------------------------------------
extern "C" void kernel_launch(void* const* d_in, const int* in_sizes, int n_in,
                              void* d_out, int out_size) {
    const float* E = (const float*)d_in[0];
    const float* U = (const float*)d_in[1];
    const int*   L = (const int*)d_in[2];
    float* out = (float*)d_out;

    k_all<<<dim3(16, 8), 128>>>(E, U, L, out);
}